// round 9
// baseline (speedup 1.0000x reference)
#include <cuda_runtime.h>

// Problem constants
#define NN 4
#define CC 256
#define HW 20480            // 128*160
#define PP (NN*HW)          // 81920 pixels
#define NB 64               // depth bins
#define CHUNK 10240         // pixels per block chunk
#define NCHUNKS (PP/CHUNK)  // 8
#define K1_BLOCKS 80

// Scratch (no device allocation allowed -> __device__ globals)
__device__ unsigned char g_idx[PP];
__device__ int   g_hist[K1_BLOCKS*NB];   // per-k1-block histogram partials
__device__ float g_sums[2*NB*CC];        // [tensor][bin][channel]

// ---------------------------------------------------------------------------
// K0: zero scratch + out (also shifts the launch pattern so ncu -s 5 -c 1
// lands on k2 in the 2nd replay).
__global__ void k0_zero(float* __restrict__ out) {
    int i = blockIdx.x * blockDim.x + threadIdx.x;   // 64*512 = 32768
    g_sums[i] = 0.f;
    if (i == 0) out[0] = 0.f;
}

// ---------------------------------------------------------------------------
// K1: bin index per pixel (uint8) + per-block histogram partials
__device__ __forceinline__ unsigned char bin_of(float d) {
    float t = d * 64.0f;                       // bin_size = 1/64 exactly
    if (t >= 0.0f && t < 64.0f) return (unsigned char)(int)t;  // trunc == ref
    return (unsigned char)64;                  // overflow/invalid bin
}

__global__ void __launch_bounds__(256) k1_idx(const float* __restrict__ depth) {
    __shared__ int hist[NB];
    const int tid = threadIdx.x;
    if (tid < NB) hist[tid] = 0;
    __syncthreads();

    const int g = blockIdx.x * 256 + tid;      // 80*256 = 20480 float4s
    float4 d = ((const float4*)depth)[g];
    uchar4 b4;
    b4.x = bin_of(d.x); b4.y = bin_of(d.y); b4.z = bin_of(d.z); b4.w = bin_of(d.w);
    ((uchar4*)g_idx)[g] = b4;
    if (b4.x < 64) atomicAdd(&hist[b4.x], 1);
    if (b4.y < 64) atomicAdd(&hist[b4.y], 1);
    if (b4.z < 64) atomicAdd(&hist[b4.z], 1);
    if (b4.w < 64) atomicAdd(&hist[b4.w], 1);
    __syncthreads();
    if (tid < NB) g_hist[blockIdx.x*NB + tid] = hist[tid];
}

// ---------------------------------------------------------------------------
// K2: streaming segment-sum.
// Block = 128 threads = 4 warps = 4 channels; warp lanes stream pixels.
// grid = (chunk 0..7, cgroup 0..63, tensor 0..1) -> 1024 blocks, 32KB smem,
// 7 blocks/SM -> 1036 capacity = single balanced wave.
// 8 independent LDGs issued up-front per iteration (MLP_p1 ~ 8) before the
// smem RMWs. Private smem column per thread: acc[bin][tid] (bank = tid%32,
// conflict-free, race-free RMW, no atomics in the hot loop).
__global__ void __launch_bounds__(128) k2_accum(const float* __restrict__ S,
                                                const float* __restrict__ T) {
    extern __shared__ float acc[];             // [NB][128] = 32 KB
    const int tid  = threadIdx.x;
    const int warp = tid >> 5;
    const int lane = tid & 31;
    const int chunk = blockIdx.x;              // 0..7
    const int n   = chunk >> 1;
    const int hw0 = (chunk & 1) * CHUNK;
    const int c   = blockIdx.y * 4 + warp;     // this warp's channel

    const unsigned char* __restrict__ ib = g_idx + n*HW + hw0;
    const float* __restrict__ src =
        (blockIdx.z ? T : S) + ((long)(n*CC + c))*HW + hw0;

    for (int i = tid; i < NB*128; i += 128) acc[i] = 0.f;
    __syncthreads();

    for (int it = 0; it < CHUNK/512; ++it) {   // 20 iters, 16 px/lane/iter
        const int p = it*512 + lane*4;
        // 8 independent global loads first -> deep MLP
        float4 v0 = *(const float4*)(src + p);
        float4 v1 = *(const float4*)(src + p + 128);
        float4 v2 = *(const float4*)(src + p + 256);
        float4 v3 = *(const float4*)(src + p + 384);
        uchar4 c0 = *(const uchar4*)(ib + p);
        uchar4 c1 = *(const uchar4*)(ib + p + 128);
        uchar4 c2 = *(const uchar4*)(ib + p + 256);
        uchar4 c3 = *(const uchar4*)(ib + p + 384);

        if (c0.x < 64) acc[(int)c0.x*128 + tid] += v0.x;
        if (c0.y < 64) acc[(int)c0.y*128 + tid] += v0.y;
        if (c0.z < 64) acc[(int)c0.z*128 + tid] += v0.z;
        if (c0.w < 64) acc[(int)c0.w*128 + tid] += v0.w;
        if (c1.x < 64) acc[(int)c1.x*128 + tid] += v1.x;
        if (c1.y < 64) acc[(int)c1.y*128 + tid] += v1.y;
        if (c1.z < 64) acc[(int)c1.z*128 + tid] += v1.z;
        if (c1.w < 64) acc[(int)c1.w*128 + tid] += v1.w;
        if (c2.x < 64) acc[(int)c2.x*128 + tid] += v2.x;
        if (c2.y < 64) acc[(int)c2.y*128 + tid] += v2.y;
        if (c2.z < 64) acc[(int)c2.z*128 + tid] += v2.z;
        if (c2.w < 64) acc[(int)c2.w*128 + tid] += v2.w;
        if (c3.x < 64) acc[(int)c3.x*128 + tid] += v3.x;
        if (c3.y < 64) acc[(int)c3.y*128 + tid] += v3.y;
        if (c3.z < 64) acc[(int)c3.z*128 + tid] += v3.z;
        if (c3.w < 64) acc[(int)c3.w*128 + tid] += v3.w;
    }
    __syncthreads();

    // Tail reduce: lane l sums bins l and l+32 across this warp's 32 columns.
    // Rotation (j+lane)&31 keeps all lanes on distinct banks every step.
    const float* aw = acc + warp*32;
    float s0 = 0.f, s1 = 0.f;
    #pragma unroll
    for (int j = 0; j < 32; ++j) {
        const int col = (j + lane) & 31;
        s0 += aw[lane*128 + col];
        s1 += aw[(lane + 32)*128 + col];
    }
    float* dst = g_sums + blockIdx.z*NB*CC + c;
    atomicAdd(dst + lane*CC,        s0);
    atomicAdd(dst + (lane + 32)*CC, s1);
}

// ---------------------------------------------------------------------------
// K3 (fused protos + loss): 64 blocks. Each block normalizes ALL 128 protos
// into its own smem (g_sums is L2-resident), then computes Gram row i for S
// and T and accumulates the squared difference.
__global__ void __launch_bounds__(256) k3_loss(float* __restrict__ out) {
    extern __shared__ float prot[];            // [2*NB][CC] = 128 KB
    __shared__ float cnt_part[4][NB];
    __shared__ float inv_cnt[NB];
    const int tid = threadIdx.x, warp = tid >> 5, lane = tid & 31;

    // counts from k1 partials: 256 threads = 64 bins x 4 groups, 20 rows each
    {
        const int bin = tid & 63, grp = tid >> 6;
        int cnt = 0;
        #pragma unroll 5
        for (int p = grp*20; p < grp*20 + 20; ++p) cnt += g_hist[p*NB + bin];
        cnt_part[grp][bin] = (float)cnt;
    }
    __syncthreads();
    if (tid < NB) {
        float cnt = cnt_part[0][tid] + cnt_part[1][tid]
                  + cnt_part[2][tid] + cnt_part[3][tid];
        inv_cnt[tid] = 1.0f / fmaxf(cnt, 1.0f);
    }
    __syncthreads();

    // normalize all 128 (tensor,bin) rows; warp per row
    for (int r = warp; r < 2*NB; r += 8) {
        const float* __restrict__ s = g_sums + r*CC;
        const float ic = inv_cnt[r & 63];
        float m[8]; float ss = 0.f;
        #pragma unroll
        for (int k = 0; k < 8; ++k) { m[k] = s[lane + 32*k] * ic; ss += m[k]*m[k]; }
        #pragma unroll
        for (int o = 16; o; o >>= 1) ss += __shfl_xor_sync(0xffffffffu, ss, o);
        const float inv = 1.0f / fmaxf(sqrtf(ss), 1e-12f);
        #pragma unroll
        for (int k = 0; k < 8; ++k) prot[r*CC + lane + 32*k] = m[k] * inv;
    }
    __syncthreads();

    // Gram row i: loss contribution sum_j (pSi.pSj - pTi.pTj)^2
    const int i = blockIdx.x;
    const float* pSi = prot + i*CC;
    const float* pTi = prot + (NB + i)*CC;
    float accv = 0.f;
    for (int j = warp; j < NB; j += 8) {
        const float* qS = prot + j*CC;
        const float* qT = prot + (NB + j)*CC;
        float sS = 0.f, sT = 0.f;
        #pragma unroll
        for (int k = lane; k < CC; k += 32) { sS += pSi[k]*qS[k]; sT += pTi[k]*qT[k]; }
        #pragma unroll
        for (int o = 16; o; o >>= 1) {
            sS += __shfl_xor_sync(0xffffffffu, sS, o);
            sT += __shfl_xor_sync(0xffffffffu, sT, o);
        }
        if (lane == 0) { const float d = sS - sT; accv += d*d; }
    }
    if (lane == 0) atomicAdd(out, accv * (1.0f/(NB*NB)));
}

// ---------------------------------------------------------------------------
extern "C" void kernel_launch(void* const* d_in, const int* in_sizes, int n_in,
                              void* d_out, int out_size) {
    (void)in_sizes; (void)n_in; (void)out_size;
    const float* S     = (const float*)d_in[0];
    const float* T     = (const float*)d_in[1];
    const float* depth = (const float*)d_in[2];
    float* out = (float*)d_out;

    cudaFuncSetAttribute(k3_loss, cudaFuncAttributeMaxDynamicSharedMemorySize,
                         2*NB*CC*(int)sizeof(float));

    k0_zero<<<64, 512>>>(out);
    k1_idx<<<K1_BLOCKS, 256>>>(depth);
    k2_accum<<<dim3(NCHUNKS, CC/4, 2), 128, NB*128*sizeof(float)>>>(S, T);
    k3_loss<<<NB, 256, 2*NB*CC*sizeof(float)>>>(out);
}